// round 2
// baseline (speedup 1.0000x reference)
#include <cuda_runtime.h>
#include <cuda_bf16.h>
#include <cstdint>

#define B_ 4
#define N_ 16384
#define M_ 16384
#define K_ 16
#define C_ 64
#define O_ 64
#define G_ 8

// ---------------- device scratch (no allocations allowed) -------------------
__device__ __align__(16) float g_WkP[C_ * G_];
__device__ __align__(16) float g_bkP[G_];
__device__ __align__(16) float g_WqP[C_ * G_];
__device__ __align__(16) float g_cw2P[O_ * G_];
__device__ __align__(16) float g_qconst[G_];
__device__ __align__(16) float g_xv[(size_t)B_ * N_ * O_];   // x_v per point
__device__ __align__(16) float g_kgp[(size_t)B_ * N_ * G_];  // x_k @ we_w1' (+bias)
__device__ __align__(16) float g_qw[(size_t)B_ * M_ * G_];   // (cpr - x_q)@we_w1' + we_b

// ============================================================================
// k0: fold we_w1*we_s through Wk, Wq, cpe_w2; fold biases.  1 block, 64 thr.
// ============================================================================
__global__ void k0_fold(const float* __restrict__ Wq, const float* __restrict__ bq,
                        const float* __restrict__ Wk, const float* __restrict__ bk,
                        const float* __restrict__ cpe_w2, const float* __restrict__ cpe_b2,
                        const float* __restrict__ we_w1, const float* __restrict__ we_s,
                        const float* __restrict__ we_b)
{
    __shared__ float w1p[O_][G_];
    int t = threadIdx.x;  // 0..63
    #pragma unroll
    for (int g = 0; g < G_; g++) w1p[t][g] = we_w1[t * G_ + g] * we_s[g];
    __syncthreads();

    float accK[G_], accQ[G_], accC[G_];
    #pragma unroll
    for (int g = 0; g < G_; g++) { accK[g] = 0.f; accQ[g] = 0.f; accC[g] = 0.f; }
    for (int o = 0; o < O_; o++) {
        float wk = Wk[t * O_ + o];
        float wq = Wq[t * O_ + o];
        float cw = cpe_w2[t * O_ + o];
        #pragma unroll
        for (int g = 0; g < G_; g++) {
            accK[g] = fmaf(wk, w1p[o][g], accK[g]);
            accQ[g] = fmaf(wq, w1p[o][g], accQ[g]);
            accC[g] = fmaf(cw, w1p[o][g], accC[g]);
        }
    }
    #pragma unroll
    for (int g = 0; g < G_; g++) {
        g_WkP[t * G_ + g]  = accK[g];
        g_WqP[t * G_ + g]  = accQ[g];
        g_cw2P[t * G_ + g] = accC[g];
    }
    if (t < G_) {
        float bkp = 0.f, bqp = 0.f, cb2p = 0.f;
        for (int o = 0; o < O_; o++) {
            bkp  = fmaf(bk[o],      w1p[o][t], bkp);
            bqp  = fmaf(bq[o],      w1p[o][t], bqp);
            cb2p = fmaf(cpe_b2[o],  w1p[o][t], cb2p);
        }
        g_bkP[t]    = bkp;
        g_qconst[t] = cb2p - bqp + we_b[t];
    }
}

// ============================================================================
// k1: per-point x_v = fea^T@Wv + bv and kgp = fea^T@WkP + bkP.
// grid (N/64, B), block 256.  Tile 64 points in shared.
// ============================================================================
__global__ void __launch_bounds__(256) k1_points(const float* __restrict__ fea,
                                                 const float* __restrict__ Wv,
                                                 const float* __restrict__ bv)
{
    __shared__ float sfea[C_][64];
    __shared__ float sWv[C_][O_];
    __shared__ float sWkP[C_][G_];
    int b  = blockIdx.y;
    int n0 = blockIdx.x * 64;
    int t  = threadIdx.x;

    const float* fbase = fea + (size_t)b * C_ * N_ + n0;
    for (int i = t; i < C_ * 64; i += 256) {
        int c = i >> 6, n = i & 63;
        sfea[c][n] = fbase[(size_t)c * N_ + n];
    }
    for (int i = t; i < C_ * O_; i += 256) sWv[i >> 6][i & 63] = Wv[i];
    for (int i = t; i < C_ * G_; i += 256) sWkP[i >> 3][i & 7] = g_WkP[i];
    __syncthreads();

    int n = t & 63, q = t >> 6;
    int ob = q * 16;
    int g0 = 2 * q;
    float acc[16];
    #pragma unroll
    for (int u = 0; u < 16; u++) acc[u] = bv[ob + u];
    float ak0 = g_bkP[g0], ak1 = g_bkP[g0 + 1];

    #pragma unroll 4
    for (int c = 0; c < C_; c++) {
        float f = sfea[c][n];
        #pragma unroll
        for (int u = 0; u < 16; u++) acc[u] = fmaf(f, sWv[c][ob + u], acc[u]);
        ak0 = fmaf(f, sWkP[c][g0],     ak0);
        ak1 = fmaf(f, sWkP[c][g0 + 1], ak1);
    }

    float* xvo = &g_xv[((size_t)b * N_ + n0 + n) * O_ + ob];
    #pragma unroll
    for (int u = 0; u < 16; u += 4)
        *(float4*)(xvo + u) = make_float4(acc[u], acc[u + 1], acc[u + 2], acc[u + 3]);
    *(float2*)&g_kgp[((size_t)b * N_ + n0 + n) * G_ + g0] = make_float2(ak0, ak1);
}

// ============================================================================
// k2: per-center qw = relu_cpe@cw2P - cfea^T@WqP + qconst.
// grid (M/64, B), block 256.
// ============================================================================
__global__ void __launch_bounds__(256) k2_centers(const float* __restrict__ cfea,
                                                  const float* __restrict__ cpos,
                                                  const float* __restrict__ cpe_w1,
                                                  const float* __restrict__ cpe_s,
                                                  const float* __restrict__ cpe_b)
{
    __shared__ float sfea[C_][64];
    __shared__ float sWqP[C_][G_];
    __shared__ float scw2P[O_][G_];
    __shared__ float sw1[3][O_];
    __shared__ float ss[O_], sb[O_];
    __shared__ float sqc[G_];

    int b  = blockIdx.y;
    int m0 = blockIdx.x * 64;
    int t  = threadIdx.x;

    const float* fbase = cfea + (size_t)b * C_ * M_ + m0;
    for (int i = t; i < C_ * 64; i += 256) {
        int c = i >> 6, m = i & 63;
        sfea[c][m] = fbase[(size_t)c * M_ + m];
    }
    for (int i = t; i < C_ * G_; i += 256) { sWqP[i >> 3][i & 7] = g_WqP[i]; scw2P[i >> 3][i & 7] = g_cw2P[i]; }
    for (int i = t; i < 3 * O_; i += 256) sw1[i >> 6][i & 63] = cpe_w1[i];
    for (int i = t; i < O_;     i += 256) { ss[i] = cpe_s[i]; sb[i] = cpe_b[i]; }
    if (t < G_) sqc[t] = g_qconst[t];
    __syncthreads();

    int m = t & 63, q = t >> 6, g0 = 2 * q;
    float a0 = sqc[g0], a1 = sqc[g0 + 1];

    #pragma unroll 4
    for (int c = 0; c < C_; c++) {
        float f = sfea[c][m];
        a0 = fmaf(-f, sWqP[c][g0],     a0);
        a1 = fmaf(-f, sWqP[c][g0 + 1], a1);
    }
    const float* cp = cpos + ((size_t)b * M_ + m0 + m) * 3;
    float x = cp[0], y = cp[1], z = cp[2];
    #pragma unroll 4
    for (int o = 0; o < O_; o++) {
        float d  = fmaf(z, sw1[2][o], fmaf(y, sw1[1][o], x * sw1[0][o]));
        float rc = fmaxf(fmaf(d, ss[o], sb[o]), 0.f);
        a0 = fmaf(rc, scw2P[o][g0],     a0);
        a1 = fmaf(rc, scw2P[o][g0 + 1], a1);
    }
    *(float2*)&g_qw[((size_t)b * M_ + m0 + m) * G_ + g0] = make_float2(a0, a1);
}

// ============================================================================
// k3: main attention. One warp per center, 8 centers per 256-thread block.
// grid (M/8, B).
// ============================================================================
__global__ void __launch_bounds__(256) k3_main(
    const float* __restrict__ cpos, const float* __restrict__ pos,
    const int*   __restrict__ idx,
    const float* __restrict__ pe_w1, const float* __restrict__ pe_s, const float* __restrict__ pe_b,
    const float* __restrict__ pe_w2, const float* __restrict__ pe_b2,
    const float* __restrict__ we_w2, const float* __restrict__ we_b2,
    float* __restrict__ out)
{
    __shared__ float s_pew2[64 * 66];                 // [j][o], row-padded to 66
    __shared__ float s_pes[64], s_peb[64], s_peb2[64];
    __shared__ float s_wew2[64];                      // [g'][g]
    __shared__ float s_web2[8];
    __shared__ int   s_nidx[8][16];
    __shared__ float s_npos[8][16][3];
    __shared__ __align__(16) float s_w[8][16][8];     // softmax weights
    __shared__ float s_S[8][8 * 66];                  // S[g][j], row pad 66
    __shared__ float s_out[64][8];                    // [o][warp]

    int b = blockIdx.y;
    int m_base = blockIdx.x * 8;
    int t = threadIdx.x;
    int w = t >> 5, l = t & 31;
    int m = m_base + w;

    // ---- cooperative constant loads ----
    for (int i = t; i < 64 * 64; i += 256) { int j = i >> 6, o = i & 63; s_pew2[j * 66 + o] = pe_w2[i]; }
    for (int i = t; i < 64; i += 256) { s_pes[i] = pe_s[i]; s_peb[i] = pe_b[i]; s_peb2[i] = pe_b2[i]; }
    if (t < 64) s_wew2[t] = we_w2[t];
    if (t < 8)  s_web2[t] = we_b2[t];

    // ---- per-warp neighbor setup ----
    float cx = cpos[((size_t)b * M_ + m) * 3 + 0];
    float cy = cpos[((size_t)b * M_ + m) * 3 + 1];
    float cz = cpos[((size_t)b * M_ + m) * 3 + 2];
    if (l < 16) {
        int n = idx[((size_t)b * M_ + m) * K_ + l];
        s_nidx[w][l] = n;
        const float* pp = pos + ((size_t)b * N_ + n) * 3;
        s_npos[w][l][0] = pp[0] - cx;
        s_npos[w][l][1] = pp[1] - cy;
        s_npos[w][l][2] = pp[2] - cz;
    }
    __syncthreads();

    // ---- load qw (broadcast) ----
    const float4* qwp = (const float4*)&g_qw[((size_t)b * M_ + m) * G_];
    float4 qa = qwp[0], qb = qwp[1];
    float qw[8] = {qa.x, qa.y, qa.z, qa.w, qb.x, qb.y, qb.z, qb.w};

    // ---- Phase A: logits + softmax.  lane -> (k = l>>1, g-quad = (l&1)*4) ----
    {
        int k  = l >> 1;
        int c4 = (l & 1) * 4;
        int n  = s_nidx[w][k];
        const float4* kgp = (const float4*)&g_kgp[((size_t)b * N_ + n) * G_];
        float4 k0 = kgp[0], k1 = kgp[1];
        float h[8];
        h[0] = fmaxf(k0.x + qw[0], 0.f); h[1] = fmaxf(k0.y + qw[1], 0.f);
        h[2] = fmaxf(k0.z + qw[2], 0.f); h[3] = fmaxf(k0.w + qw[3], 0.f);
        h[4] = fmaxf(k1.x + qw[4], 0.f); h[5] = fmaxf(k1.y + qw[5], 0.f);
        h[6] = fmaxf(k1.z + qw[6], 0.f); h[7] = fmaxf(k1.w + qw[7], 0.f);

        float lg[4];
        #pragma unroll
        for (int u = 0; u < 4; u++) {
            int g = c4 + u;
            float s = s_web2[g];
            #pragma unroll
            for (int j = 0; j < 8; j++) s = fmaf(h[j], s_wew2[j * 8 + g], s);
            lg[u] = s;
        }
        // softmax over k (16 lanes with same bit0), butterfly on masks 2,4,8,16
        float mx[4] = {lg[0], lg[1], lg[2], lg[3]};
        #pragma unroll
        for (int mask = 2; mask <= 16; mask <<= 1) {
            #pragma unroll
            for (int u = 0; u < 4; u++)
                mx[u] = fmaxf(mx[u], __shfl_xor_sync(0xffffffffu, mx[u], mask));
        }
        float e[4], sm[4];
        #pragma unroll
        for (int u = 0; u < 4; u++) { e[u] = __expf(lg[u] - mx[u]); sm[u] = e[u]; }
        #pragma unroll
        for (int mask = 2; mask <= 16; mask <<= 1) {
            #pragma unroll
            for (int u = 0; u < 4; u++)
                sm[u] += __shfl_xor_sync(0xffffffffu, sm[u], mask);
        }
        float4 wv = make_float4(e[0] / sm[0], e[1] / sm[1], e[2] / sm[2], e[3] / sm[3]);
        *(float4*)&s_w[w][k][c4] = wv;
    }
    __syncwarp();

    // ---- Phase B: S[g][j] = sum_k w[k][g] * t[k][j].  lane owns j0=2l, j1=2l+1 ----
    {
        int j0 = 2 * l, j1 = j0 + 1;
        float wx0 = pe_w1[j0], wy0 = pe_w1[64 + j0], wz0 = pe_w1[128 + j0];
        float wx1 = pe_w1[j1], wy1 = pe_w1[64 + j1], wz1 = pe_w1[128 + j1];
        float ps0 = s_pes[j0], pb0 = s_peb[j0];
        float ps1 = s_pes[j1], pb1 = s_peb[j1];
        float S0[8], S1[8];
        #pragma unroll
        for (int g = 0; g < 8; g++) { S0[g] = 0.f; S1[g] = 0.f; }

        #pragma unroll
        for (int kk = 0; kk < 16; kk++) {
            float nx = s_npos[w][kk][0], ny = s_npos[w][kk][1], nz = s_npos[w][kk][2];
            float d0 = fmaf(nz, wz0, fmaf(ny, wy0, nx * wx0));
            float d1 = fmaf(nz, wz1, fmaf(ny, wy1, nx * wx1));
            float t0 = fmaxf(fmaf(d0, ps0, pb0), 0.f);
            float t1 = fmaxf(fmaf(d1, ps1, pb1), 0.f);
            float4 wa = *(const float4*)&s_w[w][kk][0];
            float4 wb = *(const float4*)&s_w[w][kk][4];
            S0[0] = fmaf(t0, wa.x, S0[0]); S1[0] = fmaf(t1, wa.x, S1[0]);
            S0[1] = fmaf(t0, wa.y, S0[1]); S1[1] = fmaf(t1, wa.y, S1[1]);
            S0[2] = fmaf(t0, wa.z, S0[2]); S1[2] = fmaf(t1, wa.z, S1[2]);
            S0[3] = fmaf(t0, wa.w, S0[3]); S1[3] = fmaf(t1, wa.w, S1[3]);
            S0[4] = fmaf(t0, wb.x, S0[4]); S1[4] = fmaf(t1, wb.x, S1[4]);
            S0[5] = fmaf(t0, wb.y, S0[5]); S1[5] = fmaf(t1, wb.y, S1[5]);
            S0[6] = fmaf(t0, wb.z, S0[6]); S1[6] = fmaf(t1, wb.z, S1[6]);
            S0[7] = fmaf(t0, wb.w, S0[7]); S1[7] = fmaf(t1, wb.w, S1[7]);
        }
        #pragma unroll
        for (int g = 0; g < 8; g++) {
            s_S[w][g * 66 + j0] = S0[g];
            s_S[w][g * 66 + j1] = S1[g];
        }
    }
    __syncwarp();

    // ---- Phase C: out[o] = pe_b2[o] + S[g]@w2[:,o] + sum_k w[k][g]*xv[n_k][o] ----
    {
        int o0 = 2 * l;
        int g  = l >> 2;
        float a0 = s_peb2[o0], a1 = s_peb2[o0 + 1];
        const float* Sg = &s_S[w][g * 66];
        #pragma unroll 8
        for (int j = 0; j < 64; j++) {
            float  sv = Sg[j];
            float2 w2 = *(const float2*)&s_pew2[j * 66 + o0];
            a0 = fmaf(sv, w2.x, a0);
            a1 = fmaf(sv, w2.y, a1);
        }
        #pragma unroll
        for (int kk = 0; kk < 16; kk++) {
            float wk = s_w[w][kk][g];
            const float2 xv = *(const float2*)&g_xv[((size_t)b * N_ + s_nidx[w][kk]) * O_ + o0];
            a0 = fmaf(wk, xv.x, a0);
            a1 = fmaf(wk, xv.y, a1);
        }
        s_out[o0][w]     = a0;
        s_out[o0 + 1][w] = a1;
    }
    __syncthreads();

    // ---- coalesced transposed store: out[b][o][m] ----
    {
        int o = t >> 2, part = t & 3;
        float2 v = make_float2(s_out[o][part * 2], s_out[o][part * 2 + 1]);
        *(float2*)&out[((size_t)b * O_ + o) * M_ + m_base + part * 2] = v;
    }
}

// ============================================================================
extern "C" void kernel_launch(void* const* d_in, const int* in_sizes, int n_in,
                              void* d_out, int out_size)
{
    const float* center_pos = (const float*)d_in[0];
    const float* center_fea = (const float*)d_in[1];
    const float* pos        = (const float*)d_in[2];
    const float* fea        = (const float*)d_in[3];
    const int*   idx        = (const int*)  d_in[4];
    const float* Wq   = (const float*)d_in[5];
    const float* bq   = (const float*)d_in[6];
    const float* Wk   = (const float*)d_in[7];
    const float* bk   = (const float*)d_in[8];
    const float* Wv   = (const float*)d_in[9];
    const float* bv   = (const float*)d_in[10];
    const float* cpe_w1 = (const float*)d_in[11];
    const float* cpe_s  = (const float*)d_in[12];
    const float* cpe_b  = (const float*)d_in[13];
    const float* cpe_w2 = (const float*)d_in[14];
    const float* cpe_b2 = (const float*)d_in[15];
    const float* pe_w1  = (const float*)d_in[16];
    const float* pe_s   = (const float*)d_in[17];
    const float* pe_b   = (const float*)d_in[18];
    const float* pe_w2  = (const float*)d_in[19];
    const float* pe_b2  = (const float*)d_in[20];
    const float* we_w1  = (const float*)d_in[21];
    const float* we_s   = (const float*)d_in[22];
    const float* we_b   = (const float*)d_in[23];
    const float* we_w2  = (const float*)d_in[24];
    const float* we_b2  = (const float*)d_in[25];
    float* out = (float*)d_out;

    k0_fold<<<1, 64>>>(Wq, bq, Wk, bk, cpe_w2, cpe_b2, we_w1, we_s, we_b);

    dim3 g1(N_ / 64, B_);
    k1_points<<<g1, 256>>>(fea, Wv, bv);

    dim3 g2(M_ / 64, B_);
    k2_centers<<<g2, 256>>>(center_fea, center_pos, cpe_w1, cpe_s, cpe_b);

    dim3 g3(M_ / 8, B_);
    k3_main<<<g3, 256>>>(center_pos, pos, idx,
                         pe_w1, pe_s, pe_b, pe_w2, pe_b2,
                         we_w2, we_b2, out);
}

// round 3
// speedup vs baseline: 1.1777x; 1.1777x over previous
#include <cuda_runtime.h>
#include <cuda_bf16.h>
#include <cstdint>

#define B_ 4
#define N_ 16384
#define M_ 16384
#define K_ 16
#define C_ 64
#define O_ 64
#define G_ 8

// ---------------- device scratch (no allocations allowed) -------------------
__device__ __align__(16) float g_WkP[C_ * G_];
__device__ __align__(16) float g_bkP[G_];
__device__ __align__(16) float g_WqP[C_ * G_];
__device__ __align__(16) float g_cw2P[O_ * G_];
__device__ __align__(16) float g_qconst[G_];
__device__ __align__(16) float g_xv[(size_t)B_ * N_ * O_];   // x_v per point
__device__ __align__(16) float g_kgp[(size_t)B_ * N_ * G_];  // x_k @ we_w1' (+bias)
__device__ __align__(16) float g_qw[(size_t)B_ * M_ * G_];   // (cpr - x_q)@we_w1' + we_b

// ============================================================================
// k0: fold we_w1*we_s through Wk, Wq, cpe_w2; fold biases.  1 block, 64 thr.
// ============================================================================
__global__ void k0_fold(const float* __restrict__ Wq, const float* __restrict__ bq,
                        const float* __restrict__ Wk, const float* __restrict__ bk,
                        const float* __restrict__ cpe_w2, const float* __restrict__ cpe_b2,
                        const float* __restrict__ we_w1, const float* __restrict__ we_s,
                        const float* __restrict__ we_b)
{
    __shared__ float w1p[O_][G_];
    int t = threadIdx.x;  // 0..63
    #pragma unroll
    for (int g = 0; g < G_; g++) w1p[t][g] = we_w1[t * G_ + g] * we_s[g];
    __syncthreads();

    float accK[G_], accQ[G_], accC[G_];
    #pragma unroll
    for (int g = 0; g < G_; g++) { accK[g] = 0.f; accQ[g] = 0.f; accC[g] = 0.f; }
    for (int o = 0; o < O_; o++) {
        float wk = Wk[t * O_ + o];
        float wq = Wq[t * O_ + o];
        float cw = cpe_w2[t * O_ + o];
        #pragma unroll
        for (int g = 0; g < G_; g++) {
            accK[g] = fmaf(wk, w1p[o][g], accK[g]);
            accQ[g] = fmaf(wq, w1p[o][g], accQ[g]);
            accC[g] = fmaf(cw, w1p[o][g], accC[g]);
        }
    }
    #pragma unroll
    for (int g = 0; g < G_; g++) {
        g_WkP[t * G_ + g]  = accK[g];
        g_WqP[t * G_ + g]  = accQ[g];
        g_cw2P[t * G_ + g] = accC[g];
    }
    if (t < G_) {
        float bkp = 0.f, bqp = 0.f, cb2p = 0.f;
        for (int o = 0; o < O_; o++) {
            bkp  = fmaf(bk[o],      w1p[o][t], bkp);
            bqp  = fmaf(bq[o],      w1p[o][t], bqp);
            cb2p = fmaf(cpe_b2[o],  w1p[o][t], cb2p);
        }
        g_bkP[t]    = bkp;
        g_qconst[t] = cb2p - bqp + we_b[t];
    }
}

// ============================================================================
// k1: per-point x_v = fea^T@Wv + bv and kgp = fea^T@WkP + bkP.
// grid (N/64, B), block 256.  Tile 64 points in shared.
// ============================================================================
__global__ void __launch_bounds__(256) k1_points(const float* __restrict__ fea,
                                                 const float* __restrict__ Wv,
                                                 const float* __restrict__ bv)
{
    __shared__ float sfea[C_][64];
    __shared__ float sWv[C_][O_];
    __shared__ float sWkP[C_][G_];
    int b  = blockIdx.y;
    int n0 = blockIdx.x * 64;
    int t  = threadIdx.x;

    const float* fbase = fea + (size_t)b * C_ * N_ + n0;
    for (int i = t; i < C_ * 64; i += 256) {
        int c = i >> 6, n = i & 63;
        sfea[c][n] = fbase[(size_t)c * N_ + n];
    }
    for (int i = t; i < C_ * O_; i += 256) sWv[i >> 6][i & 63] = Wv[i];
    for (int i = t; i < C_ * G_; i += 256) sWkP[i >> 3][i & 7] = g_WkP[i];
    __syncthreads();

    int n = t & 63, q = t >> 6;
    int ob = q * 16;
    int g0 = 2 * q;
    float acc[16];
    #pragma unroll
    for (int u = 0; u < 16; u++) acc[u] = bv[ob + u];
    float ak0 = g_bkP[g0], ak1 = g_bkP[g0 + 1];

    #pragma unroll 4
    for (int c = 0; c < C_; c++) {
        float f = sfea[c][n];
        #pragma unroll
        for (int u = 0; u < 16; u++) acc[u] = fmaf(f, sWv[c][ob + u], acc[u]);
        ak0 = fmaf(f, sWkP[c][g0],     ak0);
        ak1 = fmaf(f, sWkP[c][g0 + 1], ak1);
    }

    float* xvo = &g_xv[((size_t)b * N_ + n0 + n) * O_ + ob];
    #pragma unroll
    for (int u = 0; u < 16; u += 4)
        *(float4*)(xvo + u) = make_float4(acc[u], acc[u + 1], acc[u + 2], acc[u + 3]);
    *(float2*)&g_kgp[((size_t)b * N_ + n0 + n) * G_ + g0] = make_float2(ak0, ak1);
}

// ============================================================================
// k2: per-center qw = relu_cpe@cw2P - cfea^T@WqP + qconst.
// grid (M/64, B), block 256.
// ============================================================================
__global__ void __launch_bounds__(256) k2_centers(const float* __restrict__ cfea,
                                                  const float* __restrict__ cpos,
                                                  const float* __restrict__ cpe_w1,
                                                  const float* __restrict__ cpe_s,
                                                  const float* __restrict__ cpe_b)
{
    __shared__ float sfea[C_][64];
    __shared__ float sWqP[C_][G_];
    __shared__ float scw2P[O_][G_];
    __shared__ float sw1[3][O_];
    __shared__ float ss[O_], sb[O_];
    __shared__ float sqc[G_];

    int b  = blockIdx.y;
    int m0 = blockIdx.x * 64;
    int t  = threadIdx.x;

    const float* fbase = cfea + (size_t)b * C_ * M_ + m0;
    for (int i = t; i < C_ * 64; i += 256) {
        int c = i >> 6, m = i & 63;
        sfea[c][m] = fbase[(size_t)c * M_ + m];
    }
    for (int i = t; i < C_ * G_; i += 256) { sWqP[i >> 3][i & 7] = g_WqP[i]; scw2P[i >> 3][i & 7] = g_cw2P[i]; }
    for (int i = t; i < 3 * O_; i += 256) sw1[i >> 6][i & 63] = cpe_w1[i];
    for (int i = t; i < O_;     i += 256) { ss[i] = cpe_s[i]; sb[i] = cpe_b[i]; }
    if (t < G_) sqc[t] = g_qconst[t];
    __syncthreads();

    int m = t & 63, q = t >> 6, g0 = 2 * q;
    float a0 = sqc[g0], a1 = sqc[g0 + 1];

    #pragma unroll 4
    for (int c = 0; c < C_; c++) {
        float f = sfea[c][m];
        a0 = fmaf(-f, sWqP[c][g0],     a0);
        a1 = fmaf(-f, sWqP[c][g0 + 1], a1);
    }
    const float* cp = cpos + ((size_t)b * M_ + m0 + m) * 3;
    float x = cp[0], y = cp[1], z = cp[2];
    #pragma unroll 4
    for (int o = 0; o < O_; o++) {
        float d  = fmaf(z, sw1[2][o], fmaf(y, sw1[1][o], x * sw1[0][o]));
        float rc = fmaxf(fmaf(d, ss[o], sb[o]), 0.f);
        a0 = fmaf(rc, scw2P[o][g0],     a0);
        a1 = fmaf(rc, scw2P[o][g0 + 1], a1);
    }
    *(float2*)&g_qw[((size_t)b * M_ + m0 + m) * G_ + g0] = make_float2(a0, a1);
}

// ============================================================================
// k3: main attention. TWO centers per warp, 8 warps -> 16 centers per block.
// grid (M/16, B), block 256.
// ============================================================================
__global__ void __launch_bounds__(256) k3_main(
    const float* __restrict__ cpos, const float* __restrict__ pos,
    const int*   __restrict__ idx,
    const float* __restrict__ pe_w1, const float* __restrict__ pe_s, const float* __restrict__ pe_b,
    const float* __restrict__ pe_w2, const float* __restrict__ pe_b2,
    const float* __restrict__ we_w2, const float* __restrict__ we_b2,
    float* __restrict__ out)
{
    __shared__ __align__(16) float s_pew2[64 * 66];      // [j][o], pad 66
    __shared__ float s_pes[64], s_peb[64], s_peb2[64];
    __shared__ float s_wew2[64];                          // [j'][g]
    __shared__ float s_web2[8];
    __shared__ int   s_nidx[16][16];
    __shared__ __align__(16) float4 s_npos[16][16];
    __shared__ __align__(16) float s_w[16][16][8];        // softmax weights per center
    __shared__ __align__(16) float s_S[8][2][8][68];      // [warp][c][g][j], pad 68
    __shared__ float s_out[64][20];                       // [o][center]

    int b = blockIdx.y;
    int m_base = blockIdx.x * 16;
    int t = threadIdx.x;
    int w = t >> 5, l = t & 31;

    // ---- cooperative constant loads ----
    for (int i = t; i < 64 * 64; i += 256) { int j = i >> 6, o = i & 63; s_pew2[j * 66 + o] = pe_w2[i]; }
    for (int i = t; i < 64; i += 256) { s_pes[i] = pe_s[i]; s_peb[i] = pe_b[i]; s_peb2[i] = pe_b2[i]; }
    if (t < 64) s_wew2[t] = we_w2[t];
    if (t < 8)  s_web2[t] = we_b2[t];

    // ---- per-warp neighbor setup: lanes 0-15 -> c=0, lanes 16-31 -> c=1 ----
    {
        int c  = l >> 4;
        int k  = l & 15;
        int cc = w * 2 + c;
        int m  = m_base + cc;
        int n  = idx[((size_t)b * M_ + m) * K_ + k];
        s_nidx[cc][k] = n;
        const float* pp = pos  + ((size_t)b * N_ + n) * 3;
        const float* cp = cpos + ((size_t)b * M_ + m) * 3;
        s_npos[cc][k] = make_float4(pp[0] - cp[0], pp[1] - cp[1], pp[2] - cp[2], 0.f);
    }
    __syncthreads();

    // ---- Phase A: logits + softmax for both centers ----
    #pragma unroll
    for (int c = 0; c < 2; c++) {
        int cc = w * 2 + c;
        int m  = m_base + cc;
        const float4* qwp = (const float4*)&g_qw[((size_t)b * M_ + m) * G_];
        float4 qa = qwp[0], qb = qwp[1];

        int k  = l >> 1;
        int c4 = (l & 1) * 4;
        int n  = s_nidx[cc][k];
        const float4* kgp = (const float4*)&g_kgp[((size_t)b * N_ + n) * G_];
        float4 k0 = kgp[0], k1 = kgp[1];
        float h[8];
        h[0] = fmaxf(k0.x + qa.x, 0.f); h[1] = fmaxf(k0.y + qa.y, 0.f);
        h[2] = fmaxf(k0.z + qa.z, 0.f); h[3] = fmaxf(k0.w + qa.w, 0.f);
        h[4] = fmaxf(k1.x + qb.x, 0.f); h[5] = fmaxf(k1.y + qb.y, 0.f);
        h[6] = fmaxf(k1.z + qb.z, 0.f); h[7] = fmaxf(k1.w + qb.w, 0.f);

        float lg[4];
        #pragma unroll
        for (int u = 0; u < 4; u++) {
            int g = c4 + u;
            float s = s_web2[g];
            #pragma unroll
            for (int j = 0; j < 8; j++) s = fmaf(h[j], s_wew2[j * 8 + g], s);
            lg[u] = s;
        }
        float mx[4] = {lg[0], lg[1], lg[2], lg[3]};
        #pragma unroll
        for (int mask = 2; mask <= 16; mask <<= 1)
            #pragma unroll
            for (int u = 0; u < 4; u++)
                mx[u] = fmaxf(mx[u], __shfl_xor_sync(0xffffffffu, mx[u], mask));
        float e[4], sm[4];
        #pragma unroll
        for (int u = 0; u < 4; u++) { e[u] = __expf(lg[u] - mx[u]); sm[u] = e[u]; }
        #pragma unroll
        for (int mask = 2; mask <= 16; mask <<= 1)
            #pragma unroll
            for (int u = 0; u < 4; u++)
                sm[u] += __shfl_xor_sync(0xffffffffu, sm[u], mask);
        *(float4*)&s_w[cc][k][c4] =
            make_float4(e[0] / sm[0], e[1] / sm[1], e[2] / sm[2], e[3] / sm[3]);
    }
    __syncwarp();

    // ---- Phase B: S[c][g][j] = sum_k w[k][g]*t[k][j]; lane owns j0=2l, j1 ----
    {
        int j0 = 2 * l, j1 = j0 + 1;
        float wx0 = pe_w1[j0], wy0 = pe_w1[64 + j0], wz0 = pe_w1[128 + j0];
        float wx1 = pe_w1[j1], wy1 = pe_w1[64 + j1], wz1 = pe_w1[128 + j1];
        float ps0 = s_pes[j0], pb0 = s_peb[j0];
        float ps1 = s_pes[j1], pb1 = s_peb[j1];

        #pragma unroll
        for (int c = 0; c < 2; c++) {
            int cc = w * 2 + c;
            float S0[8], S1[8];
            #pragma unroll
            for (int g = 0; g < 8; g++) { S0[g] = 0.f; S1[g] = 0.f; }

            #pragma unroll
            for (int kk = 0; kk < 16; kk++) {
                float4 np = s_npos[cc][kk];
                float d0 = fmaf(np.z, wz0, fmaf(np.y, wy0, np.x * wx0));
                float d1 = fmaf(np.z, wz1, fmaf(np.y, wy1, np.x * wx1));
                float t0 = fmaxf(fmaf(d0, ps0, pb0), 0.f);
                float t1 = fmaxf(fmaf(d1, ps1, pb1), 0.f);
                float4 wa = *(const float4*)&s_w[cc][kk][0];
                float4 wb = *(const float4*)&s_w[cc][kk][4];
                S0[0] = fmaf(t0, wa.x, S0[0]); S1[0] = fmaf(t1, wa.x, S1[0]);
                S0[1] = fmaf(t0, wa.y, S0[1]); S1[1] = fmaf(t1, wa.y, S1[1]);
                S0[2] = fmaf(t0, wa.z, S0[2]); S1[2] = fmaf(t1, wa.z, S1[2]);
                S0[3] = fmaf(t0, wa.w, S0[3]); S1[3] = fmaf(t1, wa.w, S1[3]);
                S0[4] = fmaf(t0, wb.x, S0[4]); S1[4] = fmaf(t1, wb.x, S1[4]);
                S0[5] = fmaf(t0, wb.y, S0[5]); S1[5] = fmaf(t1, wb.y, S1[5]);
                S0[6] = fmaf(t0, wb.z, S0[6]); S1[6] = fmaf(t1, wb.z, S1[6]);
                S0[7] = fmaf(t0, wb.w, S0[7]); S1[7] = fmaf(t1, wb.w, S1[7]);
            }
            #pragma unroll
            for (int g = 0; g < 8; g++) {
                s_S[w][c][g][j0] = S0[g];
                s_S[w][c][g][j1] = S1[g];
            }
        }
    }
    __syncwarp();

    // ---- Phase C: out[o] = pe_b2 + S[g]@W2[:,o] + sum_k w[k][g]*xv[nk][o] ----
    {
        int o0 = 2 * l;
        int g  = l >> 2;
        float a00 = s_peb2[o0], a01 = s_peb2[o0 + 1];   // center c=0
        float a10 = a00,        a11 = a01;              // center c=1
        const float* Sg0 = &s_S[w][0][g][0];
        const float* Sg1 = &s_S[w][1][g][0];

        #pragma unroll
        for (int j = 0; j < 64; j += 4) {
            float4 sa = *(const float4*)(Sg0 + j);
            float4 sb = *(const float4*)(Sg1 + j);
            float2 w0 = *(const float2*)&s_pew2[(j + 0) * 66 + o0];
            float2 w1 = *(const float2*)&s_pew2[(j + 1) * 66 + o0];
            float2 w2 = *(const float2*)&s_pew2[(j + 2) * 66 + o0];
            float2 w3 = *(const float2*)&s_pew2[(j + 3) * 66 + o0];
            a00 = fmaf(sa.x, w0.x, a00); a01 = fmaf(sa.x, w0.y, a01);
            a10 = fmaf(sb.x, w0.x, a10); a11 = fmaf(sb.x, w0.y, a11);
            a00 = fmaf(sa.y, w1.x, a00); a01 = fmaf(sa.y, w1.y, a01);
            a10 = fmaf(sb.y, w1.x, a10); a11 = fmaf(sb.y, w1.y, a11);
            a00 = fmaf(sa.z, w2.x, a00); a01 = fmaf(sa.z, w2.y, a01);
            a10 = fmaf(sb.z, w2.x, a10); a11 = fmaf(sb.z, w2.y, a11);
            a00 = fmaf(sa.w, w3.x, a00); a01 = fmaf(sa.w, w3.y, a01);
            a10 = fmaf(sb.w, w3.x, a10); a11 = fmaf(sb.w, w3.y, a11);
        }

        #pragma unroll
        for (int c = 0; c < 2; c++) {
            int cc = w * 2 + c;
            float ax = (c == 0) ? a00 : a10;
            float ay = (c == 0) ? a01 : a11;
            const float* xvb = &g_xv[((size_t)b * N_) * O_];
            #pragma unroll
            for (int kk = 0; kk < 16; kk++) {
                float wk = s_w[cc][kk][g];
                const float2 xv = *(const float2*)&xvb[(size_t)s_nidx[cc][kk] * O_ + o0];
                ax = fmaf(wk, xv.x, ax);
                ay = fmaf(wk, xv.y, ay);
            }
            s_out[o0][cc]     = ax;
            s_out[o0 + 1][cc] = ay;
        }
    }
    __syncthreads();

    // ---- coalesced transposed store: out[b][o][m_base + 0..15] ----
    {
        int mm = t & 15;
        #pragma unroll
        for (int o = t >> 4; o < 64; o += 16)
            out[((size_t)b * O_ + o) * M_ + m_base + mm] = s_out[o][mm];
    }
}

// ============================================================================
extern "C" void kernel_launch(void* const* d_in, const int* in_sizes, int n_in,
                              void* d_out, int out_size)
{
    const float* center_pos = (const float*)d_in[0];
    const float* center_fea = (const float*)d_in[1];
    const float* pos        = (const float*)d_in[2];
    const float* fea        = (const float*)d_in[3];
    const int*   idx        = (const int*)  d_in[4];
    const float* Wq   = (const float*)d_in[5];
    const float* bq   = (const float*)d_in[6];
    const float* Wk   = (const float*)d_in[7];
    const float* bk   = (const float*)d_in[8];
    const float* Wv   = (const float*)d_in[9];
    const float* bv   = (const float*)d_in[10];
    const float* cpe_w1 = (const float*)d_in[11];
    const float* cpe_s  = (const float*)d_in[12];
    const float* cpe_b  = (const float*)d_in[13];
    const float* cpe_w2 = (const float*)d_in[14];
    const float* cpe_b2 = (const float*)d_in[15];
    const float* pe_w1  = (const float*)d_in[16];
    const float* pe_s   = (const float*)d_in[17];
    const float* pe_b   = (const float*)d_in[18];
    const float* pe_w2  = (const float*)d_in[19];
    const float* pe_b2  = (const float*)d_in[20];
    const float* we_w1  = (const float*)d_in[21];
    const float* we_s   = (const float*)d_in[22];
    const float* we_b   = (const float*)d_in[23];
    const float* we_w2  = (const float*)d_in[24];
    const float* we_b2  = (const float*)d_in[25];
    float* out = (float*)d_out;

    k0_fold<<<1, 64>>>(Wq, bq, Wk, bk, cpe_w2, cpe_b2, we_w1, we_s, we_b);

    dim3 g1(N_ / 64, B_);
    k1_points<<<g1, 256>>>(fea, Wv, bv);

    dim3 g2(M_ / 64, B_);
    k2_centers<<<g2, 256>>>(center_fea, center_pos, cpe_w1, cpe_s, cpe_b);

    dim3 g3(M_ / 16, B_);
    k3_main<<<g3, 256>>>(center_pos, pos, idx,
                         pe_w1, pe_s, pe_b, pe_w2, pe_b2,
                         we_w2, we_b2, out);
}

// round 4
// speedup vs baseline: 1.2093x; 1.0268x over previous
#include <cuda_runtime.h>
#include <cuda_bf16.h>
#include <cstdint>

#define B_ 4
#define N_ 16384
#define M_ 16384
#define K_ 16
#define C_ 64
#define O_ 64
#define G_ 8

// ---------------- device scratch (no allocations allowed) -------------------
__device__ __align__(16) float g_WkP[C_ * G_];
__device__ __align__(16) float g_bkP[G_];
__device__ __align__(16) float g_WqP[C_ * G_];
__device__ __align__(16) float g_cw2P[O_ * G_];
__device__ __align__(16) float g_qconst[G_];
__device__ __align__(16) float g_xv[(size_t)B_ * N_ * O_];   // x_v per point
__device__ __align__(16) float g_kgp[(size_t)B_ * N_ * G_];  // x_k @ we_w1' (+bias)
__device__ __align__(16) float g_qw[(size_t)B_ * M_ * G_];   // (cpr - x_q)@we_w1' + we_b

// ============================================================================
// k0: fold we_w1*we_s through Wk, Wq, cpe_w2; fold biases.  1 block, 64 thr.
// ============================================================================
__global__ void k0_fold(const float* __restrict__ Wq, const float* __restrict__ bq,
                        const float* __restrict__ Wk, const float* __restrict__ bk,
                        const float* __restrict__ cpe_w2, const float* __restrict__ cpe_b2,
                        const float* __restrict__ we_w1, const float* __restrict__ we_s,
                        const float* __restrict__ we_b)
{
    __shared__ float w1p[O_][G_];
    int t = threadIdx.x;  // 0..63
    #pragma unroll
    for (int g = 0; g < G_; g++) w1p[t][g] = we_w1[t * G_ + g] * we_s[g];
    __syncthreads();

    float accK[G_], accQ[G_], accC[G_];
    #pragma unroll
    for (int g = 0; g < G_; g++) { accK[g] = 0.f; accQ[g] = 0.f; accC[g] = 0.f; }
    for (int o = 0; o < O_; o++) {
        float wk = Wk[t * O_ + o];
        float wq = Wq[t * O_ + o];
        float cw = cpe_w2[t * O_ + o];
        #pragma unroll
        for (int g = 0; g < G_; g++) {
            accK[g] = fmaf(wk, w1p[o][g], accK[g]);
            accQ[g] = fmaf(wq, w1p[o][g], accQ[g]);
            accC[g] = fmaf(cw, w1p[o][g], accC[g]);
        }
    }
    #pragma unroll
    for (int g = 0; g < G_; g++) {
        g_WkP[t * G_ + g]  = accK[g];
        g_WqP[t * G_ + g]  = accQ[g];
        g_cw2P[t * G_ + g] = accC[g];
    }
    if (t < G_) {
        float bkp = 0.f, bqp = 0.f, cb2p = 0.f;
        for (int o = 0; o < O_; o++) {
            bkp  = fmaf(bk[o],      w1p[o][t], bkp);
            bqp  = fmaf(bq[o],      w1p[o][t], bqp);
            cb2p = fmaf(cpe_b2[o],  w1p[o][t], cb2p);
        }
        g_bkP[t]    = bkp;
        g_qconst[t] = cb2p - bqp + we_b[t];
    }
}

// ============================================================================
// k1: per-point x_v = fea^T@Wv + bv and kgp = fea^T@WkP + bkP.
// ============================================================================
__global__ void __launch_bounds__(256) k1_points(const float* __restrict__ fea,
                                                 const float* __restrict__ Wv,
                                                 const float* __restrict__ bv)
{
    __shared__ float sfea[C_][64];
    __shared__ float sWv[C_][O_];
    __shared__ float sWkP[C_][G_];
    int b  = blockIdx.y;
    int n0 = blockIdx.x * 64;
    int t  = threadIdx.x;

    const float* fbase = fea + (size_t)b * C_ * N_ + n0;
    for (int i = t; i < C_ * 64; i += 256) {
        int c = i >> 6, n = i & 63;
        sfea[c][n] = fbase[(size_t)c * N_ + n];
    }
    for (int i = t; i < C_ * O_; i += 256) sWv[i >> 6][i & 63] = Wv[i];
    for (int i = t; i < C_ * G_; i += 256) sWkP[i >> 3][i & 7] = g_WkP[i];
    __syncthreads();

    int n = t & 63, q = t >> 6;
    int ob = q * 16;
    int g0 = 2 * q;
    float acc[16];
    #pragma unroll
    for (int u = 0; u < 16; u++) acc[u] = bv[ob + u];
    float ak0 = g_bkP[g0], ak1 = g_bkP[g0 + 1];

    #pragma unroll 4
    for (int c = 0; c < C_; c++) {
        float f = sfea[c][n];
        #pragma unroll
        for (int u = 0; u < 16; u++) acc[u] = fmaf(f, sWv[c][ob + u], acc[u]);
        ak0 = fmaf(f, sWkP[c][g0],     ak0);
        ak1 = fmaf(f, sWkP[c][g0 + 1], ak1);
    }

    float* xvo = &g_xv[((size_t)b * N_ + n0 + n) * O_ + ob];
    #pragma unroll
    for (int u = 0; u < 16; u += 4)
        *(float4*)(xvo + u) = make_float4(acc[u], acc[u + 1], acc[u + 2], acc[u + 3]);
    *(float2*)&g_kgp[((size_t)b * N_ + n0 + n) * G_ + g0] = make_float2(ak0, ak1);
}

// ============================================================================
// k2: per-center qw = relu_cpe@cw2P - cfea^T@WqP + qconst.
// ============================================================================
__global__ void __launch_bounds__(256) k2_centers(const float* __restrict__ cfea,
                                                  const float* __restrict__ cpos,
                                                  const float* __restrict__ cpe_w1,
                                                  const float* __restrict__ cpe_s,
                                                  const float* __restrict__ cpe_b)
{
    __shared__ float sfea[C_][64];
    __shared__ float sWqP[C_][G_];
    __shared__ float scw2P[O_][G_];
    __shared__ float sw1[3][O_];
    __shared__ float ss[O_], sb[O_];
    __shared__ float sqc[G_];

    int b  = blockIdx.y;
    int m0 = blockIdx.x * 64;
    int t  = threadIdx.x;

    const float* fbase = cfea + (size_t)b * C_ * M_ + m0;
    for (int i = t; i < C_ * 64; i += 256) {
        int c = i >> 6, m = i & 63;
        sfea[c][m] = fbase[(size_t)c * M_ + m];
    }
    for (int i = t; i < C_ * G_; i += 256) { sWqP[i >> 3][i & 7] = g_WqP[i]; scw2P[i >> 3][i & 7] = g_cw2P[i]; }
    for (int i = t; i < 3 * O_; i += 256) sw1[i >> 6][i & 63] = cpe_w1[i];
    for (int i = t; i < O_;     i += 256) { ss[i] = cpe_s[i]; sb[i] = cpe_b[i]; }
    if (t < G_) sqc[t] = g_qconst[t];
    __syncthreads();

    int m = t & 63, q = t >> 6, g0 = 2 * q;
    float a0 = sqc[g0], a1 = sqc[g0 + 1];

    #pragma unroll 4
    for (int c = 0; c < C_; c++) {
        float f = sfea[c][m];
        a0 = fmaf(-f, sWqP[c][g0],     a0);
        a1 = fmaf(-f, sWqP[c][g0 + 1], a1);
    }
    const float* cp = cpos + ((size_t)b * M_ + m0 + m) * 3;
    float x = cp[0], y = cp[1], z = cp[2];
    #pragma unroll 4
    for (int o = 0; o < O_; o++) {
        float d  = fmaf(z, sw1[2][o], fmaf(y, sw1[1][o], x * sw1[0][o]));
        float rc = fmaxf(fmaf(d, ss[o], sb[o]), 0.f);
        a0 = fmaf(rc, scw2P[o][g0],     a0);
        a1 = fmaf(rc, scw2P[o][g0 + 1], a1);
    }
    *(float2*)&g_qw[((size_t)b * M_ + m0 + m) * G_ + g0] = make_float2(a0, a1);
}

// ============================================================================
// k3: main attention. 2 centers/warp, 16 centers/block. Dynamic smem 54.5KB,
// j-chunked S staging -> 4 blocks/SM.
// ============================================================================
__global__ void __launch_bounds__(256, 4) k3_main(
    const float* __restrict__ cpos, const float* __restrict__ pos,
    const int*   __restrict__ idx,
    const float* __restrict__ pe_w1, const float* __restrict__ pe_s, const float* __restrict__ pe_b,
    const float* __restrict__ pe_w2, const float* __restrict__ pe_b2,
    const float* __restrict__ we_w2, const float* __restrict__ we_b2,
    float* __restrict__ out)
{
    extern __shared__ __align__(16) char dyns[];
    float*  s_pew2 = (float*)dyns;                 // [64][68]          4352 f
    float*  s_stg  = s_pew2 + 64 * 68;             // [8][2][8][36]     4608 f
    float*  s_w    = s_stg  + 4608;                // [16][16][8]       2048 f
    float4* s_npos = (float4*)(s_w + 2048);        // [16][16]          1024 f
    float*  s_out  = (float*)(s_npos + 256);       // [16][68]          1088 f
    int*    s_nidx = (int*)(s_out + 1088);         // [16][16]           256 i
    float*  s_pes  = (float*)(s_nidx + 256);       // 64
    float*  s_peb  = s_pes + 64;                   // 64
    float*  s_peb2 = s_peb + 64;                   // 64
    float*  s_wew2 = s_peb2 + 64;                  // 64
    float*  s_web2 = s_wew2 + 64;                  // 8

    int b = blockIdx.y;
    int m_base = blockIdx.x * 16;
    int t = threadIdx.x;
    int w = t >> 5, l = t & 31;

    // ---- cooperative constant loads ----
    for (int i = t; i < 64 * 64; i += 256) { int j = i >> 6, o = i & 63; s_pew2[j * 68 + o] = pe_w2[i]; }
    for (int i = t; i < 64; i += 256) { s_pes[i] = pe_s[i]; s_peb[i] = pe_b[i]; s_peb2[i] = pe_b2[i]; }
    if (t < 64) s_wew2[t] = we_w2[t];
    if (t < 8)  s_web2[t] = we_b2[t];

    int half = l >> 4;            // 0/1: which center of the warp's pair
    int cc   = w * 2 + half;
    int m    = m_base + cc;

    // ---- neighbor setup: lane (half, k=l&15) ----
    {
        int k = l & 15;
        int n = idx[((size_t)b * M_ + m) * K_ + k];
        s_nidx[cc * 16 + k] = n;
        const float* pp = pos  + ((size_t)b * N_ + n) * 3;
        const float* cp = cpos + ((size_t)b * M_ + m) * 3;
        s_npos[cc * 16 + k] = make_float4(pp[0] - cp[0], pp[1] - cp[1], pp[2] - cp[2], 0.f);
    }
    __syncthreads();

    // ---- Phase A: logits + softmax, both centers in parallel across halves ----
    {
        int k = l & 15;
        int n = s_nidx[cc * 16 + k];
        const float4* qwp = (const float4*)&g_qw[((size_t)b * M_ + m) * G_];
        float4 qa = qwp[0], qb = qwp[1];
        const float4* kgp = (const float4*)&g_kgp[((size_t)b * N_ + n) * G_];
        float4 k0 = kgp[0], k1 = kgp[1];
        float h[8];
        h[0] = fmaxf(k0.x + qa.x, 0.f); h[1] = fmaxf(k0.y + qa.y, 0.f);
        h[2] = fmaxf(k0.z + qa.z, 0.f); h[3] = fmaxf(k0.w + qa.w, 0.f);
        h[4] = fmaxf(k1.x + qb.x, 0.f); h[5] = fmaxf(k1.y + qb.y, 0.f);
        h[6] = fmaxf(k1.z + qb.z, 0.f); h[7] = fmaxf(k1.w + qb.w, 0.f);

        float4 lgA = *(const float4*)&s_web2[0];
        float4 lgB = *(const float4*)&s_web2[4];
        #pragma unroll
        for (int j = 0; j < 8; j++) {
            float hj = h[j];
            float4 wA = *(const float4*)&s_wew2[j * 8];
            float4 wB = *(const float4*)&s_wew2[j * 8 + 4];
            lgA.x = fmaf(hj, wA.x, lgA.x); lgA.y = fmaf(hj, wA.y, lgA.y);
            lgA.z = fmaf(hj, wA.z, lgA.z); lgA.w = fmaf(hj, wA.w, lgA.w);
            lgB.x = fmaf(hj, wB.x, lgB.x); lgB.y = fmaf(hj, wB.y, lgB.y);
            lgB.z = fmaf(hj, wB.z, lgB.z); lgB.w = fmaf(hj, wB.w, lgB.w);
        }
        float lg[8] = {lgA.x, lgA.y, lgA.z, lgA.w, lgB.x, lgB.y, lgB.z, lgB.w};
        float mx[8];
        #pragma unroll
        for (int u = 0; u < 8; u++) mx[u] = lg[u];
        #pragma unroll
        for (int mask = 1; mask <= 8; mask <<= 1)
            #pragma unroll
            for (int u = 0; u < 8; u++)
                mx[u] = fmaxf(mx[u], __shfl_xor_sync(0xffffffffu, mx[u], mask));
        float e[8], sm[8];
        #pragma unroll
        for (int u = 0; u < 8; u++) { e[u] = __expf(lg[u] - mx[u]); sm[u] = e[u]; }
        #pragma unroll
        for (int mask = 1; mask <= 8; mask <<= 1)
            #pragma unroll
            for (int u = 0; u < 8; u++)
                sm[u] += __shfl_xor_sync(0xffffffffu, sm[u], mask);
        float* wp = &s_w[(cc * 16 + k) * 8];
        *(float4*)&wp[0] = make_float4(e[0] / sm[0], e[1] / sm[1], e[2] / sm[2], e[3] / sm[3]);
        *(float4*)&wp[4] = make_float4(e[4] / sm[4], e[5] / sm[5], e[6] / sm[6], e[7] / sm[7]);
    }
    __syncwarp();

    // ---- Phase B: S[c][g][j] in registers; lane owns j0=2l, j1=2l+1 ----
    float S0[2][8], S1[2][8];
    {
        int j0 = 2 * l, j1 = j0 + 1;
        float wx0 = pe_w1[j0], wy0 = pe_w1[64 + j0], wz0 = pe_w1[128 + j0];
        float wx1 = pe_w1[j1], wy1 = pe_w1[64 + j1], wz1 = pe_w1[128 + j1];
        float ps0 = s_pes[j0], pb0 = s_peb[j0];
        float ps1 = s_pes[j1], pb1 = s_peb[j1];

        #pragma unroll
        for (int c = 0; c < 2; c++) {
            int ccB = w * 2 + c;
            #pragma unroll
            for (int g = 0; g < 8; g++) { S0[c][g] = 0.f; S1[c][g] = 0.f; }
            #pragma unroll
            for (int kk = 0; kk < 16; kk++) {
                float4 np = s_npos[ccB * 16 + kk];
                float d0 = fmaf(np.z, wz0, fmaf(np.y, wy0, np.x * wx0));
                float d1 = fmaf(np.z, wz1, fmaf(np.y, wy1, np.x * wx1));
                float t0 = fmaxf(fmaf(d0, ps0, pb0), 0.f);
                float t1 = fmaxf(fmaf(d1, ps1, pb1), 0.f);
                const float* wp = &s_w[(ccB * 16 + kk) * 8];
                float4 wa = *(const float4*)&wp[0];
                float4 wb = *(const float4*)&wp[4];
                S0[c][0] = fmaf(t0, wa.x, S0[c][0]); S1[c][0] = fmaf(t1, wa.x, S1[c][0]);
                S0[c][1] = fmaf(t0, wa.y, S0[c][1]); S1[c][1] = fmaf(t1, wa.y, S1[c][1]);
                S0[c][2] = fmaf(t0, wa.z, S0[c][2]); S1[c][2] = fmaf(t1, wa.z, S1[c][2]);
                S0[c][3] = fmaf(t0, wa.w, S0[c][3]); S1[c][3] = fmaf(t1, wa.w, S1[c][3]);
                S0[c][4] = fmaf(t0, wb.x, S0[c][4]); S1[c][4] = fmaf(t1, wb.x, S1[c][4]);
                S0[c][5] = fmaf(t0, wb.y, S0[c][5]); S1[c][5] = fmaf(t1, wb.y, S1[c][5]);
                S0[c][6] = fmaf(t0, wb.z, S0[c][6]); S1[c][6] = fmaf(t1, wb.z, S1[c][6]);
                S0[c][7] = fmaf(t0, wb.w, S0[c][7]); S1[c][7] = fmaf(t1, wb.w, S1[c][7]);
            }
        }
    }

    // ---- Phase C: chunked over j (2 chunks of 32). lane: (half, o0=(l&15)*4) ----
    {
        int lo = l & 15;
        int o0 = lo * 4;
        int g  = lo >> 1;                      // = o0 >> 3
        float4 acc = *(const float4*)&s_peb2[o0];
        float* stg = &s_stg[((w * 2 + half) * 8 + g) * 36];
        int myChunk = l >> 4;                  // which chunk this lane's S regs belong to
        int jl = (l & 15) * 2;                 // local j within chunk

        #pragma unroll
        for (int ch = 0; ch < 2; ch++) {
            if (myChunk == ch) {
                #pragma unroll
                for (int c = 0; c < 2; c++) {
                    float* dst = &s_stg[((w * 2 + c) * 8) * 36];
                    #pragma unroll
                    for (int gg = 0; gg < 8; gg++)
                        *(float2*)&dst[gg * 36 + jl] = make_float2(S0[c][gg], S1[c][gg]);
                }
            }
            __syncwarp();
            int jb = ch * 32;
            #pragma unroll
            for (int jq = 0; jq < 32; jq += 4) {
                float4 sv  = *(const float4*)&stg[jq];
                const float* wrow = &s_pew2[(jb + jq) * 68 + o0];
                float4 w20 = *(const float4*)(wrow);
                float4 w21 = *(const float4*)(wrow + 68);
                float4 w22 = *(const float4*)(wrow + 136);
                float4 w23 = *(const float4*)(wrow + 204);
                acc.x = fmaf(sv.x, w20.x, acc.x); acc.y = fmaf(sv.x, w20.y, acc.y);
                acc.z = fmaf(sv.x, w20.z, acc.z); acc.w = fmaf(sv.x, w20.w, acc.w);
                acc.x = fmaf(sv.y, w21.x, acc.x); acc.y = fmaf(sv.y, w21.y, acc.y);
                acc.z = fmaf(sv.y, w21.z, acc.z); acc.w = fmaf(sv.y, w21.w, acc.w);
                acc.x = fmaf(sv.z, w22.x, acc.x); acc.y = fmaf(sv.z, w22.y, acc.y);
                acc.z = fmaf(sv.z, w22.z, acc.z); acc.w = fmaf(sv.z, w22.w, acc.w);
                acc.x = fmaf(sv.w, w23.x, acc.x); acc.y = fmaf(sv.w, w23.y, acc.y);
                acc.z = fmaf(sv.w, w23.z, acc.z); acc.w = fmaf(sv.w, w23.w, acc.w);
            }
            __syncwarp();
        }

        // xv gather part
        const float* xvb = &g_xv[((size_t)b * N_) * O_];
        #pragma unroll
        for (int kk = 0; kk < 16; kk++) {
            int   n  = s_nidx[cc * 16 + kk];
            float wk = s_w[(cc * 16 + kk) * 8 + g];
            float4 xv = *(const float4*)&xvb[(size_t)n * O_ + o0];
            acc.x = fmaf(wk, xv.x, acc.x);
            acc.y = fmaf(wk, xv.y, acc.y);
            acc.z = fmaf(wk, xv.z, acc.z);
            acc.w = fmaf(wk, xv.w, acc.w);
        }
        *(float4*)&s_out[cc * 68 + o0] = acc;
    }
    __syncthreads();

    // ---- coalesced transposed store: out[b][o][m_base + 0..15] ----
    {
        int mm = t & 15;
        #pragma unroll
        for (int o = t >> 4; o < 64; o += 16)
            out[((size_t)b * O_ + o) * M_ + m_base + mm] = s_out[mm * 68 + o];
    }
}

// ============================================================================
extern "C" void kernel_launch(void* const* d_in, const int* in_sizes, int n_in,
                              void* d_out, int out_size)
{
    const float* center_pos = (const float*)d_in[0];
    const float* center_fea = (const float*)d_in[1];
    const float* pos        = (const float*)d_in[2];
    const float* fea        = (const float*)d_in[3];
    const int*   idx        = (const int*)  d_in[4];
    const float* Wq   = (const float*)d_in[5];
    const float* bq   = (const float*)d_in[6];
    const float* Wk   = (const float*)d_in[7];
    const float* bk   = (const float*)d_in[8];
    const float* Wv   = (const float*)d_in[9];
    const float* bv   = (const float*)d_in[10];
    const float* cpe_w1 = (const float*)d_in[11];
    const float* cpe_s  = (const float*)d_in[12];
    const float* cpe_b  = (const float*)d_in[13];
    const float* cpe_w2 = (const float*)d_in[14];
    const float* cpe_b2 = (const float*)d_in[15];
    const float* pe_w1  = (const float*)d_in[16];
    const float* pe_s   = (const float*)d_in[17];
    const float* pe_b   = (const float*)d_in[18];
    const float* pe_w2  = (const float*)d_in[19];
    const float* pe_b2  = (const float*)d_in[20];
    const float* we_w1  = (const float*)d_in[21];
    const float* we_s   = (const float*)d_in[22];
    const float* we_b   = (const float*)d_in[23];
    const float* we_w2  = (const float*)d_in[24];
    const float* we_b2  = (const float*)d_in[25];
    float* out = (float*)d_out;

    const int SMEM_K3 = 54560;
    static int attr_set = 0;
    if (!attr_set) {
        cudaFuncSetAttribute(k3_main, cudaFuncAttributeMaxDynamicSharedMemorySize, SMEM_K3);
        attr_set = 1;
    }

    k0_fold<<<1, 64>>>(Wq, bq, Wk, bk, cpe_w2, cpe_b2, we_w1, we_s, we_b);

    dim3 g1(N_ / 64, B_);
    k1_points<<<g1, 256>>>(fea, Wv, bv);

    dim3 g2(M_ / 64, B_);
    k2_centers<<<g2, 256>>>(center_fea, center_pos, cpe_w1, cpe_s, cpe_b);

    dim3 g3(M_ / 16, B_);
    k3_main<<<g3, 256, SMEM_K3>>>(center_pos, pos, idx,
                                  pe_w1, pe_s, pe_b, pe_w2, pe_b2,
                                  we_w2, we_b2, out);
}